// round 3
// baseline (speedup 1.0000x reference)
#include <cuda_runtime.h>
#include <cuda.h>
#include <cstdint>

// ChannelMultiHeadAttention, fused one-warp-per-unit tf32 MMA kernel.
//
// Shapes: x[1024,64,14,64]; per unit (b,c): 14x64 tile X.
// Algebra: energy1 (pre-LN, modulo terms constant along the normalized axis,
// which LayerNorm provably cancels) =  (w_c X) M X^T + r (X wvec)^T
//   M = Wq^T Wk, wvec = Wk^T bq, r = rowsum(w_c).  bk cancels entirely.
// Then LN, softmax(/8), out = att @ (X Wv^T + bv).

#define SEQ   14
#define EMBD  64
#define UNITS 65536
#define WPB   8
#define NBLOCKS 2048
#define NITERS  4     // 2048 * 8 * 4 = 65536

// ---- shared memory layout (float indices) ----
#define MB_OFF    0            // 4096: M in B-fragment-major layout (tf32)
#define WVB_OFF   4096         // 4096: Wv in B-fragment-major layout (tf32)
#define WVEC_OFF  8192         // 64
#define BV_OFF    8256         // 64
#define R_OFF     8320         // 16
#define LNG_OFF   8336         // 16
#define LNB_OFF   8352         // 16
#define XW_OFF    8368         // 8 warps * 16
#define XS_OFF    8496         // 8 warps * 16*68
#define XS_W      1088
#define S1_OFF    (XS_OFF + 8*XS_W)   // 17200
#define E_OFF     (S1_OFF + 8*XS_W)   // 25904
#define E_W       272                  // 16*17
#define SMEM_FLOATS (E_OFF + 8*E_W)   // 28080
#define SMEM_BYTES  (SMEM_FLOATS * 4) // 112320 B

static_assert(NBLOCKS * WPB * NITERS == UNITS, "grid covers all units");

__device__ float g_M[4096];    // M[d][d'] = sum_e Wq[e,d]*Wk[e,d']
__device__ float g_wvec[64];   // wvec[d'] = sum_e bq[e]*Wk[e,d']
__device__ float g_r[16];      // r[a] = sum_l w_c[a,l], padded to 16

__device__ __forceinline__ unsigned tf32r(float x) {
    unsigned r; asm("cvt.rna.tf32.f32 %0, %1;" : "=r"(r) : "f"(x)); return r;
}
__device__ __forceinline__ float tf32f(float x) { return __uint_as_float(tf32r(x)); }

__device__ __forceinline__ void mma8(float c[4],
                                     unsigned a0, unsigned a1, unsigned a2, unsigned a3,
                                     unsigned b0, unsigned b1) {
    asm volatile("mma.sync.aligned.m16n8k8.row.col.f32.tf32.tf32.f32 "
                 "{%0,%1,%2,%3}, {%4,%5,%6,%7}, {%8,%9}, {%0,%1,%2,%3};"
                 : "+f"(c[0]), "+f"(c[1]), "+f"(c[2]), "+f"(c[3])
                 : "r"(a0), "r"(a1), "r"(a2), "r"(a3), "r"(b0), "r"(b1));
}

// ---------------- precompute kernel (tiny, runs once per launch) ------------
__global__ void precompute_kernel(const float* __restrict__ Wq,
                                  const float* __restrict__ bq,
                                  const float* __restrict__ Wk,
                                  const float* __restrict__ w_c) {
    int i = blockIdx.x * blockDim.x + threadIdx.x;
    if (i < 4096) {
        int d = i >> 6, dp = i & 63;
        float s = 0.f;
        #pragma unroll 8
        for (int e = 0; e < 64; e++) s += Wq[e * 64 + d] * Wk[e * 64 + dp];
        g_M[i] = s;
    } else if (i < 4160) {
        int dp = i - 4096;
        float s = 0.f;
        #pragma unroll 8
        for (int e = 0; e < 64; e++) s += bq[e] * Wk[e * 64 + dp];
        g_wvec[dp] = s;
    } else if (i < 4176) {
        int a = i - 4160;
        float s = 0.f;
        if (a < 14) { for (int l = 0; l < 14; l++) s += w_c[a * 14 + l]; }
        g_r[a] = s;
    }
}

// ---------------- main fused kernel ----------------------------------------
__global__ __launch_bounds__(256) void attn_kernel(
    const float* __restrict__ x, const float* __restrict__ w_c,
    const float* __restrict__ Wv, const float* __restrict__ bv,
    const float* __restrict__ ln_g, const float* __restrict__ ln_b,
    float* __restrict__ out) {

    extern __shared__ float sm[];
    const int tid  = threadIdx.x;
    const int wid  = tid >> 5;
    const int lane = tid & 31;
    const int g    = lane >> 2;   // group id 0..7  (output row within tile)
    const int t    = lane & 3;    // thread-in-group 0..3

    // ---- stage M and Wv into B-fragment-major layout (conflict-free float2) ----
    for (int i2 = tid; i2 < 2048; i2 += 256) {
        int ln2 = i2 & 31, knt = i2 >> 5;
        int ks = knt >> 3, nt = knt & 7;
        int tt = ln2 & 3, gg = ln2 >> 2;
        int r0 = 8 * ks + tt, r1 = r0 + 4, cc = 8 * nt + gg;
        sm[MB_OFF  + 2 * i2]     = tf32f(g_M[r0 * 64 + cc]);        // B[k][n]=M[d][d']
        sm[MB_OFF  + 2 * i2 + 1] = tf32f(g_M[r1 * 64 + cc]);
        sm[WVB_OFF + 2 * i2]     = tf32f(Wv[cc * 64 + r0]);         // B[k=d][n=e]=Wv[e][d]
        sm[WVB_OFF + 2 * i2 + 1] = tf32f(Wv[cc * 64 + r1]);
    }
    for (int i = tid; i < 64; i += 256) {
        sm[WVEC_OFF + i] = g_wvec[i];
        sm[BV_OFF   + i] = bv[i];
    }
    if (tid < 16) {
        sm[R_OFF   + tid] = g_r[tid];
        sm[LNG_OFF + tid] = (tid < 14) ? ln_g[tid] : 0.f;
        sm[LNB_OFF + tid] = (tid < 14) ? ln_b[tid] : 0.f;
    }
    // w_c A-fragments live in registers (identical for every warp/unit)
    unsigned wcA[2][4];
    #pragma unroll
    for (int ks = 0; ks < 2; ks++) {
        int c0 = 8 * ks + t, c1 = c0 + 4;
        float a0 = (g     < 14 && c0 < 14) ? w_c[g * 14 + c0]       : 0.f;
        float a1 = (g + 8 < 14 && c0 < 14) ? w_c[(g + 8) * 14 + c0] : 0.f;
        float a2 = (g     < 14 && c1 < 14) ? w_c[g * 14 + c1]       : 0.f;
        float a3 = (g + 8 < 14 && c1 < 14) ? w_c[(g + 8) * 14 + c1] : 0.f;
        wcA[ks][0] = tf32r(a0); wcA[ks][1] = tf32r(a1);
        wcA[ks][2] = tf32r(a2); wcA[ks][3] = tf32r(a3);
    }
    __syncthreads();

    float* Xs = sm + XS_OFF + wid * XS_W;   // X tile, 16 rows x stride 68, tf32
    float* S1 = sm + S1_OFF + wid * XS_W;   // staging: Aw -> P -> V
    float* Eb = sm + E_OFF  + wid * E_W;    // 16x16 scores / att, stride 17
    float* Xw = sm + XW_OFF + wid * 16;
    const float2* MbF = (const float2*)(sm + MB_OFF);
    const float2* WvF = (const float2*)(sm + WVB_OFF);

    for (int it = 0; it < NITERS; it++) {
        const int u = blockIdx.x * (WPB * NITERS) + it * WPB + wid;
        const float* xg = x + (size_t)u * 896;

        // ---- load X tile (tf32-rounded), zero pad rows 14,15 ----
        #pragma unroll
        for (int i = 0; i < 7; i++) {
            int f4 = lane + 32 * i;                 // 224 float4s
            float4 v = __ldg((const float4*)xg + f4);
            int f = f4 * 4, row = f >> 6, col = f & 63;
            float* p = Xs + row * 68 + col;
            p[0] = tf32f(v.x); p[1] = tf32f(v.y); p[2] = tf32f(v.z); p[3] = tf32f(v.w);
        }
        #pragma unroll
        for (int i = lane; i < 128; i += 32) {
            Xs[(14 + (i >> 6)) * 68 + (i & 63)] = 0.f;
        }
        __syncwarp();

        // ---- Xw[j] = X[j] . wvec ----
        if (lane < 16) {
            float s = 0.f;
            if (lane < 14) {
                #pragma unroll
                for (int d = 0; d < 64; d++) s += Xs[lane * 68 + d] * sm[WVEC_OFF + d];
            }
            Xw[lane] = s;
        }

        // ---- step1: Aw = w_c @ X  -> S1 ----
        {
            float c[8][4];
            #pragma unroll
            for (int nt = 0; nt < 8; nt++) { c[nt][0]=c[nt][1]=c[nt][2]=c[nt][3]=0.f; }
            #pragma unroll
            for (int ks = 0; ks < 2; ks++) {
                #pragma unroll
                for (int nt = 0; nt < 8; nt++) {
                    unsigned b0 = __float_as_uint(Xs[(8*ks + t    ) * 68 + 8*nt + g]);
                    unsigned b1 = __float_as_uint(Xs[(8*ks + t + 4) * 68 + 8*nt + g]);
                    mma8(c[nt], wcA[ks][0], wcA[ks][1], wcA[ks][2], wcA[ks][3], b0, b1);
                }
            }
            #pragma unroll
            for (int nt = 0; nt < 8; nt++) {
                int c0 = 8 * nt + 2 * t;
                S1[g * 68 + c0]           = tf32f(c[nt][0]);
                S1[g * 68 + c0 + 1]       = tf32f(c[nt][1]);
                S1[(g + 8) * 68 + c0]     = tf32f(c[nt][2]);
                S1[(g + 8) * 68 + c0 + 1] = tf32f(c[nt][3]);
            }
            __syncwarp();
        }

        // ---- step2: P = Aw @ M -> S1 (overwrite after all reads) ----
        {
            float c[8][4];
            #pragma unroll
            for (int nt = 0; nt < 8; nt++) { c[nt][0]=c[nt][1]=c[nt][2]=c[nt][3]=0.f; }
            #pragma unroll
            for (int ks = 0; ks < 8; ks++) {
                unsigned a0 = __float_as_uint(S1[g * 68 + 8*ks + t]);
                unsigned a1 = __float_as_uint(S1[(g + 8) * 68 + 8*ks + t]);
                unsigned a2 = __float_as_uint(S1[g * 68 + 8*ks + t + 4]);
                unsigned a3 = __float_as_uint(S1[(g + 8) * 68 + 8*ks + t + 4]);
                #pragma unroll
                for (int nt = 0; nt < 8; nt++) {
                    float2 b = MbF[(ks * 8 + nt) * 32 + lane];
                    mma8(c[nt], a0, a1, a2, a3,
                         __float_as_uint(b.x), __float_as_uint(b.y));
                }
            }
            __syncwarp();
            #pragma unroll
            for (int nt = 0; nt < 8; nt++) {
                int c0 = 8 * nt + 2 * t;
                S1[g * 68 + c0]           = tf32f(c[nt][0]);
                S1[g * 68 + c0 + 1]       = tf32f(c[nt][1]);
                S1[(g + 8) * 68 + c0]     = tf32f(c[nt][2]);
                S1[(g + 8) * 68 + c0 + 1] = tf32f(c[nt][3]);
            }
            __syncwarp();
        }

        // ---- step3: E = P @ X^T -> Eb ----
        {
            float c[2][4];
            #pragma unroll
            for (int nt = 0; nt < 2; nt++) { c[nt][0]=c[nt][1]=c[nt][2]=c[nt][3]=0.f; }
            #pragma unroll
            for (int ks = 0; ks < 8; ks++) {
                unsigned a0 = __float_as_uint(S1[g * 68 + 8*ks + t]);
                unsigned a1 = __float_as_uint(S1[(g + 8) * 68 + 8*ks + t]);
                unsigned a2 = __float_as_uint(S1[g * 68 + 8*ks + t + 4]);
                unsigned a3 = __float_as_uint(S1[(g + 8) * 68 + 8*ks + t + 4]);
                #pragma unroll
                for (int nt = 0; nt < 2; nt++) {
                    unsigned b0 = __float_as_uint(Xs[(8*nt + g) * 68 + 8*ks + t]);
                    unsigned b1 = __float_as_uint(Xs[(8*nt + g) * 68 + 8*ks + t + 4]);
                    mma8(c[nt], a0, a1, a2, a3, b0, b1);
                }
            }
            #pragma unroll
            for (int nt = 0; nt < 2; nt++) {
                int c0 = 8 * nt + 2 * t;
                Eb[g * 17 + c0]           = c[nt][0];
                Eb[g * 17 + c0 + 1]       = c[nt][1];
                Eb[(g + 8) * 17 + c0]     = c[nt][2];
                Eb[(g + 8) * 17 + c0 + 1] = c[nt][3];
            }
            __syncwarp();
        }

        // ---- LayerNorm(14) + softmax(/8), one lane per row ----
        if (lane < 16) {
            if (lane < 14) {
                float e[14];
                float ra = sm[R_OFF + lane];
                float mean = 0.f;
                #pragma unroll
                for (int j = 0; j < 14; j++) {
                    e[j] = Eb[lane * 17 + j] + ra * Xw[j];
                    mean += e[j];
                }
                mean *= (1.f / 14.f);
                float var = 0.f;
                #pragma unroll
                for (int j = 0; j < 14; j++) { float d = e[j] - mean; var += d * d; }
                var *= (1.f / 14.f);
                float inv = rsqrtf(var + 1e-5f);
                float mx = -1e30f;
                #pragma unroll
                for (int j = 0; j < 14; j++) {
                    e[j] = ((e[j] - mean) * inv * sm[LNG_OFF + j] + sm[LNB_OFF + j]) * 0.125f;
                    mx = fmaxf(mx, e[j]);
                }
                float s = 0.f;
                #pragma unroll
                for (int j = 0; j < 14; j++) { e[j] = __expf(e[j] - mx); s += e[j]; }
                float is = 1.f / s;
                #pragma unroll
                for (int j = 0; j < 14; j++) Eb[lane * 17 + j] = tf32f(e[j] * is);
                Eb[lane * 17 + 14] = 0.f;
                Eb[lane * 17 + 15] = 0.f;
            } else {
                #pragma unroll
                for (int j = 0; j < 16; j++) Eb[lane * 17 + j] = 0.f;
            }
        }
        __syncwarp();

        // ---- step5: V = X @ Wv^T + bv -> S1 ----
        {
            float c[8][4];
            #pragma unroll
            for (int nt = 0; nt < 8; nt++) {
                float b0v = sm[BV_OFF + 8*nt + 2*t];
                float b1v = sm[BV_OFF + 8*nt + 2*t + 1];
                c[nt][0] = b0v; c[nt][1] = b1v; c[nt][2] = b0v; c[nt][3] = b1v;
            }
            #pragma unroll
            for (int ks = 0; ks < 8; ks++) {
                unsigned a0 = __float_as_uint(Xs[g * 68 + 8*ks + t]);
                unsigned a1 = __float_as_uint(Xs[(g + 8) * 68 + 8*ks + t]);
                unsigned a2 = __float_as_uint(Xs[g * 68 + 8*ks + t + 4]);
                unsigned a3 = __float_as_uint(Xs[(g + 8) * 68 + 8*ks + t + 4]);
                #pragma unroll
                for (int nt = 0; nt < 8; nt++) {
                    float2 b = WvF[(ks * 8 + nt) * 32 + lane];
                    mma8(c[nt], a0, a1, a2, a3,
                         __float_as_uint(b.x), __float_as_uint(b.y));
                }
            }
            __syncwarp();
            #pragma unroll
            for (int nt = 0; nt < 8; nt++) {
                int c0 = 8 * nt + 2 * t;
                S1[g * 68 + c0]           = tf32f(c[nt][0]);
                S1[g * 68 + c0 + 1]       = tf32f(c[nt][1]);
                S1[(g + 8) * 68 + c0]     = tf32f(c[nt][2]);
                S1[(g + 8) * 68 + c0 + 1] = tf32f(c[nt][3]);
            }
            __syncwarp();
        }

        // ---- step6: out = att @ V, write to gmem ----
        {
            float c[8][4];
            #pragma unroll
            for (int nt = 0; nt < 8; nt++) { c[nt][0]=c[nt][1]=c[nt][2]=c[nt][3]=0.f; }
            #pragma unroll
            for (int ks = 0; ks < 2; ks++) {
                unsigned a0 = __float_as_uint(Eb[g * 17 + 8*ks + t]);
                unsigned a1 = __float_as_uint(Eb[(g + 8) * 17 + 8*ks + t]);
                unsigned a2 = __float_as_uint(Eb[g * 17 + 8*ks + t + 4]);
                unsigned a3 = __float_as_uint(Eb[(g + 8) * 17 + 8*ks + t + 4]);
                #pragma unroll
                for (int nt = 0; nt < 8; nt++) {
                    unsigned b0 = __float_as_uint(S1[(8*ks + t    ) * 68 + 8*nt + g]);
                    unsigned b1 = __float_as_uint(S1[(8*ks + t + 4) * 68 + 8*nt + g]);
                    mma8(c[nt], a0, a1, a2, a3, b0, b1);
                }
            }
            float* og = out + (size_t)u * 896;
            #pragma unroll
            for (int nt = 0; nt < 8; nt++) {
                int c0 = 8 * nt + 2 * t;
                *(float2*)(og + g * 64 + c0) = make_float2(c[nt][0], c[nt][1]);
                if (g < 6)
                    *(float2*)(og + (g + 8) * 64 + c0) = make_float2(c[nt][2], c[nt][3]);
            }
        }
        __syncwarp();
    }
}

// ---------------- launcher --------------------------------------------------
extern "C" void kernel_launch(void* const* d_in, const int* in_sizes, int n_in,
                              void* d_out, int out_size) {
    const float* x    = (const float*)d_in[0];
    const float* w_c  = (const float*)d_in[1];
    const float* Wq   = (const float*)d_in[2];
    const float* bq   = (const float*)d_in[3];
    const float* Wk   = (const float*)d_in[4];
    // d_in[5] = bk — provably cancelled by LayerNorm mean subtraction.
    const float* Wv   = (const float*)d_in[6];
    const float* bv   = (const float*)d_in[7];
    const float* ln_g = (const float*)d_in[8];
    const float* ln_b = (const float*)d_in[9];
    float* out = (float*)d_out;

    cudaFuncSetAttribute(attn_kernel,
                         cudaFuncAttributeMaxDynamicSharedMemorySize, SMEM_BYTES);

    precompute_kernel<<<17, 256>>>(Wq, bq, Wk, w_c);
    attn_kernel<<<NBLOCKS, 256, SMEM_BYTES>>>(x, w_c, Wv, bv, ln_g, ln_b, out);
}

// round 4
// speedup vs baseline: 1.1377x; 1.1377x over previous
#include <cuda_runtime.h>
#include <cuda.h>
#include <cstdint>

// ChannelMultiHeadAttention, fused one-warp-per-unit tf32 MMA kernel. v3.
//
// Algebra (LayerNorm cancels all terms constant along the normalized axis):
//   pre-LN scores = w_c (X M X^T) + r (X wvec)^T
//     M = Wq^T Wk, wvec = Wk^T bq, r = rowsum(w_c). bk cancels entirely.
// Then LN(14), softmax(/8), out = att @ (X Wv^T + bv).
//
// v3 changes vs v2 (which was L1/LSU-bound at 88.6%):
//  - reassociated: Z = (X M) X^T first, then tiny E = w_c Z  (saves 12 MMAs
//    and a full 16x68 shared round-trip per unit)
//  - X A-fragments kept in registers for the X@M GEMM
//  - Xw computed from register fragments + quad shfl reduction
//  - float2/float4 shared stores, register prefetch of next X tile

#define SEQ   14
#define EMBD  64
#define UNITS 65536
#define WPB   8
#define NBLOCKS 2048
#define NITERS  4     // 2048 * 8 * 4 = 65536

// ---- shared memory layout (float indices) ----
#define MB_OFF    0            // 4096: M in B-fragment-major layout (tf32)
#define WVB_OFF   4096         // 4096: Wv in B-fragment-major layout (tf32)
#define WVEC_OFF  8192         // 64
#define BV_OFF    8256         // 64
#define R_OFF     8320         // 16
#define LNG_OFF   8336         // 16
#define LNB_OFF   8352         // 16
#define XW_OFF    8368         // 8 warps * 16
#define XS_OFF    8496         // 8 warps * 16*68
#define XS_W      1088
#define S1_OFF    (XS_OFF + 8*XS_W)   // staging: Y -> V
#define E_OFF     (S1_OFF + 8*XS_W)   // 16x16 scores / att, stride 17
#define E_W       272
#define SMEM_FLOATS (E_OFF + 8*E_W)
#define SMEM_BYTES  (SMEM_FLOATS * 4) // 112320 B

static_assert(NBLOCKS * WPB * NITERS == UNITS, "grid covers all units");

__device__ float g_M[4096];    // M[d][d'] = sum_e Wq[e,d]*Wk[e,d']
__device__ float g_wvec[64];   // wvec[d'] = sum_e bq[e]*Wk[e,d']
__device__ float g_r[16];      // r[a] = sum_l w_c[a,l]

__device__ __forceinline__ unsigned tf32r(float x) {
    unsigned r; asm("cvt.rna.tf32.f32 %0, %1;" : "=r"(r) : "f"(x)); return r;
}
__device__ __forceinline__ float tf32f(float x) { return __uint_as_float(tf32r(x)); }

__device__ __forceinline__ void mma8(float c[4],
                                     unsigned a0, unsigned a1, unsigned a2, unsigned a3,
                                     unsigned b0, unsigned b1) {
    asm volatile("mma.sync.aligned.m16n8k8.row.col.f32.tf32.tf32.f32 "
                 "{%0,%1,%2,%3}, {%4,%5,%6,%7}, {%8,%9}, {%0,%1,%2,%3};"
                 : "+f"(c[0]), "+f"(c[1]), "+f"(c[2]), "+f"(c[3])
                 : "r"(a0), "r"(a1), "r"(a2), "r"(a3), "r"(b0), "r"(b1));
}

// ---------------- precompute kernel (tiny, runs once per launch) ------------
__global__ void precompute_kernel(const float* __restrict__ Wq,
                                  const float* __restrict__ bq,
                                  const float* __restrict__ Wk,
                                  const float* __restrict__ w_c) {
    int i = blockIdx.x * blockDim.x + threadIdx.x;
    if (i < 4096) {
        int d = i >> 6, dp = i & 63;
        float s = 0.f;
        #pragma unroll 8
        for (int e = 0; e < 64; e++) s += Wq[e * 64 + d] * Wk[e * 64 + dp];
        g_M[i] = s;
    } else if (i < 4160) {
        int dp = i - 4096;
        float s = 0.f;
        #pragma unroll 8
        for (int e = 0; e < 64; e++) s += bq[e] * Wk[e * 64 + dp];
        g_wvec[dp] = s;
    } else if (i < 4176) {
        int a = i - 4160;
        float s = 0.f;
        if (a < 14) { for (int l = 0; l < 14; l++) s += w_c[a * 14 + l]; }
        g_r[a] = s;
    }
}

// ---------------- main fused kernel ----------------------------------------
__global__ __launch_bounds__(256, 2) void attn_kernel(
    const float* __restrict__ x, const float* __restrict__ w_c,
    const float* __restrict__ Wv, const float* __restrict__ bv,
    const float* __restrict__ ln_g, const float* __restrict__ ln_b,
    float* __restrict__ out) {

    extern __shared__ float sm[];
    const int tid  = threadIdx.x;
    const int wid  = tid >> 5;
    const int lane = tid & 31;
    const int g    = lane >> 2;   // group id 0..7
    const int t    = lane & 3;    // thread-in-group 0..3

    // ---- stage M and Wv into B-fragment-major layout (conflict-free float2) ----
    for (int i2 = tid; i2 < 2048; i2 += 256) {
        int ln2 = i2 & 31, knt = i2 >> 5;
        int ks = knt >> 3, nt = knt & 7;
        int tt = ln2 & 3, gg = ln2 >> 2;
        int r0 = 8 * ks + tt, r1 = r0 + 4, cc = 8 * nt + gg;
        sm[MB_OFF  + 2 * i2]     = tf32f(g_M[r0 * 64 + cc]);     // B[k][n]=M[d][d']
        sm[MB_OFF  + 2 * i2 + 1] = tf32f(g_M[r1 * 64 + cc]);
        sm[WVB_OFF + 2 * i2]     = tf32f(Wv[cc * 64 + r0]);      // B[k=d][n=e]=Wv[e][d]
        sm[WVB_OFF + 2 * i2 + 1] = tf32f(Wv[cc * 64 + r1]);
    }
    for (int i = tid; i < 64; i += 256) {
        sm[WVEC_OFF + i] = g_wvec[i];
        sm[BV_OFF   + i] = bv[i];
    }
    if (tid < 16) {
        sm[R_OFF   + tid] = g_r[tid];
        sm[LNG_OFF + tid] = (tid < 14) ? ln_g[tid] : 0.f;
        sm[LNB_OFF + tid] = (tid < 14) ? ln_b[tid] : 0.f;
    }
    // w_c A-fragments in registers (identical for every warp/unit)
    unsigned wcA[2][4];
    #pragma unroll
    for (int ks = 0; ks < 2; ks++) {
        int c0 = 8 * ks + t, c1 = c0 + 4;
        float a0 = (g     < 14 && c0 < 14) ? w_c[g * 14 + c0]       : 0.f;
        float a1 = (g + 8 < 14 && c0 < 14) ? w_c[(g + 8) * 14 + c0] : 0.f;
        float a2 = (g     < 14 && c1 < 14) ? w_c[g * 14 + c1]       : 0.f;
        float a3 = (g + 8 < 14 && c1 < 14) ? w_c[(g + 8) * 14 + c1] : 0.f;
        wcA[ks][0] = tf32r(a0); wcA[ks][1] = tf32r(a1);
        wcA[ks][2] = tf32r(a2); wcA[ks][3] = tf32r(a3);
    }
    __syncthreads();

    float* Xs = sm + XS_OFF + wid * XS_W;   // X tile, 16 rows x stride 68
    float* S1 = sm + S1_OFF + wid * XS_W;   // staging: Y -> V
    float* Eb = sm + E_OFF  + wid * E_W;    // 16x16 scores / att, stride 17
    float* Xw = sm + XW_OFF + wid * 16;
    const float2* MbF = (const float2*)(sm + MB_OFF);
    const float2* WvF = (const float2*)(sm + WVB_OFF);

    const int ubase = blockIdx.x * (WPB * NITERS) + wid;

    // prefetch X tile for it=0
    float4 pf[7];
    {
        const float4* xg = (const float4*)(x + (size_t)ubase * 896);
        #pragma unroll
        for (int i = 0; i < 7; i++) pf[i] = __ldg(xg + lane + 32 * i);
    }

    #pragma unroll 1
    for (int it = 0; it < NITERS; it++) {
        const int u = ubase + it * WPB;

        // ---- store X tile (tf32-rounded) + zero pad rows 14,15 ----
        #pragma unroll
        for (int i = 0; i < 7; i++) {
            int f = (lane + 32 * i) * 4;
            int row = f >> 6, col = f & 63;
            float4 v = pf[i];
            *(float4*)(Xs + row * 68 + col) =
                make_float4(tf32f(v.x), tf32f(v.y), tf32f(v.z), tf32f(v.w));
        }
        {
            int row = 14 + (lane >> 4), col = (lane & 15) * 4;
            *(float4*)(Xs + row * 68 + col) = make_float4(0.f, 0.f, 0.f, 0.f);
        }
        __syncwarp();

        // ---- X A-fragments into registers (conflict-free LDS) ----
        unsigned xA[8][4];
        #pragma unroll
        for (int ks = 0; ks < 8; ks++) {
            xA[ks][0] = __float_as_uint(Xs[g * 68 + 8 * ks + t]);
            xA[ks][1] = __float_as_uint(Xs[(g + 8) * 68 + 8 * ks + t]);
            xA[ks][2] = __float_as_uint(Xs[g * 68 + 8 * ks + t + 4]);
            xA[ks][3] = __float_as_uint(Xs[(g + 8) * 68 + 8 * ks + t + 4]);
        }

        // ---- prefetch next iteration's X tile (hide DRAM latency) ----
        if (it + 1 < NITERS) {
            const float4* xg = (const float4*)(x + (size_t)(u + WPB) * 896);
            #pragma unroll
            for (int i = 0; i < 7; i++) pf[i] = __ldg(xg + lane + 32 * i);
        }

        // ---- Xw[j] = X[j] . wvec  (from register fragments, quad reduce) ----
        {
            float s0 = 0.f, s1 = 0.f;
            #pragma unroll
            for (int ks = 0; ks < 8; ks++) {
                float w0 = sm[WVEC_OFF + 8 * ks + t];
                float w1 = sm[WVEC_OFF + 8 * ks + t + 4];
                s0 = fmaf(__uint_as_float(xA[ks][0]), w0,
                     fmaf(__uint_as_float(xA[ks][2]), w1, s0));
                s1 = fmaf(__uint_as_float(xA[ks][1]), w0,
                     fmaf(__uint_as_float(xA[ks][3]), w1, s1));
            }
            s0 += __shfl_xor_sync(0xffffffffu, s0, 1);
            s0 += __shfl_xor_sync(0xffffffffu, s0, 2);
            s1 += __shfl_xor_sync(0xffffffffu, s1, 1);
            s1 += __shfl_xor_sync(0xffffffffu, s1, 2);
            if (t == 0) { Xw[g] = s0; Xw[g + 8] = s1; }
        }

        // ---- Y = X @ M  -> S1 ----
        {
            float c[8][4];
            #pragma unroll
            for (int nt = 0; nt < 8; nt++) { c[nt][0]=c[nt][1]=c[nt][2]=c[nt][3]=0.f; }
            #pragma unroll
            for (int ks = 0; ks < 8; ks++) {
                #pragma unroll
                for (int nt = 0; nt < 8; nt++) {
                    float2 b = MbF[(ks * 8 + nt) * 32 + lane];
                    mma8(c[nt], xA[ks][0], xA[ks][1], xA[ks][2], xA[ks][3],
                         __float_as_uint(b.x), __float_as_uint(b.y));
                }
            }
            #pragma unroll
            for (int nt = 0; nt < 8; nt++) {
                int c0 = 8 * nt + 2 * t;
                *(float2*)(S1 + g * 68 + c0) =
                    make_float2(tf32f(c[nt][0]), tf32f(c[nt][1]));
                *(float2*)(S1 + (g + 8) * 68 + c0) =
                    make_float2(tf32f(c[nt][2]), tf32f(c[nt][3]));
            }
            __syncwarp();
        }

        // ---- Z = Y @ X^T -> Eb ----
        {
            float c[2][4];
            #pragma unroll
            for (int nt = 0; nt < 2; nt++) { c[nt][0]=c[nt][1]=c[nt][2]=c[nt][3]=0.f; }
            #pragma unroll
            for (int ks = 0; ks < 8; ks++) {
                unsigned a0 = __float_as_uint(S1[g * 68 + 8*ks + t]);
                unsigned a1 = __float_as_uint(S1[(g + 8) * 68 + 8*ks + t]);
                unsigned a2 = __float_as_uint(S1[g * 68 + 8*ks + t + 4]);
                unsigned a3 = __float_as_uint(S1[(g + 8) * 68 + 8*ks + t + 4]);
                #pragma unroll
                for (int nt = 0; nt < 2; nt++) {
                    unsigned b0 = __float_as_uint(Xs[(8*nt + g) * 68 + 8*ks + t]);
                    unsigned b1 = __float_as_uint(Xs[(8*nt + g) * 68 + 8*ks + t + 4]);
                    mma8(c[nt], a0, a1, a2, a3, b0, b1);
                }
            }
            #pragma unroll
            for (int nt = 0; nt < 2; nt++) {
                int c0 = 8 * nt + 2 * t;
                Eb[g * 17 + c0]           = c[nt][0];
                Eb[g * 17 + c0 + 1]       = c[nt][1];
                Eb[(g + 8) * 17 + c0]     = c[nt][2];
                Eb[(g + 8) * 17 + c0 + 1] = c[nt][3];
            }
            __syncwarp();
        }

        // ---- E = w_c @ Z  (tiny, 4 MMAs) -> Eb ----
        {
            unsigned B[2][2][2];
            #pragma unroll
            for (int ks = 0; ks < 2; ks++)
                #pragma unroll
                for (int nt = 0; nt < 2; nt++) {
                    B[ks][nt][0] = __float_as_uint(Eb[(8*ks + t) * 17 + 8*nt + g]);
                    B[ks][nt][1] = __float_as_uint(Eb[(8*ks + t + 4) * 17 + 8*nt + g]);
                }
            __syncwarp();
            float c[2][4];
            #pragma unroll
            for (int nt = 0; nt < 2; nt++) { c[nt][0]=c[nt][1]=c[nt][2]=c[nt][3]=0.f; }
            #pragma unroll
            for (int ks = 0; ks < 2; ks++)
                #pragma unroll
                for (int nt = 0; nt < 2; nt++)
                    mma8(c[nt], wcA[ks][0], wcA[ks][1], wcA[ks][2], wcA[ks][3],
                         B[ks][nt][0], B[ks][nt][1]);
            #pragma unroll
            for (int nt = 0; nt < 2; nt++) {
                int c0 = 8 * nt + 2 * t;
                Eb[g * 17 + c0]           = c[nt][0];
                Eb[g * 17 + c0 + 1]       = c[nt][1];
                Eb[(g + 8) * 17 + c0]     = c[nt][2];
                Eb[(g + 8) * 17 + c0 + 1] = c[nt][3];
            }
            __syncwarp();
        }

        // ---- LayerNorm(14) + softmax(/8), one lane per row ----
        if (lane < 16) {
            if (lane < 14) {
                float e[14];
                float ra = sm[R_OFF + lane];
                float mean = 0.f;
                #pragma unroll
                for (int j = 0; j < 14; j++) {
                    e[j] = Eb[lane * 17 + j] + ra * Xw[j];
                    mean += e[j];
                }
                mean *= (1.f / 14.f);
                float var = 0.f;
                #pragma unroll
                for (int j = 0; j < 14; j++) { float d = e[j] - mean; var += d * d; }
                var *= (1.f / 14.f);
                float inv = rsqrtf(var + 1e-5f);
                float mx = -1e30f;
                #pragma unroll
                for (int j = 0; j < 14; j++) {
                    e[j] = ((e[j] - mean) * inv * sm[LNG_OFF + j] + sm[LNB_OFF + j]) * 0.125f;
                    mx = fmaxf(mx, e[j]);
                }
                float s = 0.f;
                #pragma unroll
                for (int j = 0; j < 14; j++) { e[j] = __expf(e[j] - mx); s += e[j]; }
                float is = 1.f / s;
                #pragma unroll
                for (int j = 0; j < 14; j++) Eb[lane * 17 + j] = tf32f(e[j] * is);
                Eb[lane * 17 + 14] = 0.f;
                Eb[lane * 17 + 15] = 0.f;
            } else {
                #pragma unroll
                for (int j = 0; j < 16; j++) Eb[lane * 17 + j] = 0.f;
            }
        }
        __syncwarp();

        // ---- V = X @ Wv^T + bv -> S1 ----
        {
            float c[8][4];
            #pragma unroll
            for (int nt = 0; nt < 8; nt++) {
                float b0v = sm[BV_OFF + 8*nt + 2*t];
                float b1v = sm[BV_OFF + 8*nt + 2*t + 1];
                c[nt][0] = b0v; c[nt][1] = b1v; c[nt][2] = b0v; c[nt][3] = b1v;
            }
            #pragma unroll
            for (int ks = 0; ks < 8; ks++) {
                unsigned a0 = __float_as_uint(Xs[g * 68 + 8*ks + t]);
                unsigned a1 = __float_as_uint(Xs[(g + 8) * 68 + 8*ks + t]);
                unsigned a2 = __float_as_uint(Xs[g * 68 + 8*ks + t + 4]);
                unsigned a3 = __float_as_uint(Xs[(g + 8) * 68 + 8*ks + t + 4]);
                #pragma unroll
                for (int nt = 0; nt < 8; nt++) {
                    float2 b = WvF[(ks * 8 + nt) * 32 + lane];
                    mma8(c[nt], a0, a1, a2, a3,
                         __float_as_uint(b.x), __float_as_uint(b.y));
                }
            }
            __syncwarp();
            #pragma unroll
            for (int nt = 0; nt < 8; nt++) {
                int c0 = 8 * nt + 2 * t;
                *(float2*)(S1 + g * 68 + c0) =
                    make_float2(tf32f(c[nt][0]), tf32f(c[nt][1]));
                *(float2*)(S1 + (g + 8) * 68 + c0) =
                    make_float2(tf32f(c[nt][2]), tf32f(c[nt][3]));
            }
            __syncwarp();
        }

        // ---- out = att @ V, write to gmem ----
        {
            float c[8][4];
            #pragma unroll
            for (int nt = 0; nt < 8; nt++) { c[nt][0]=c[nt][1]=c[nt][2]=c[nt][3]=0.f; }
            #pragma unroll
            for (int ks = 0; ks < 2; ks++) {
                unsigned a0 = __float_as_uint(Eb[g * 17 + 8*ks + t]);
                unsigned a1 = __float_as_uint(Eb[(g + 8) * 17 + 8*ks + t]);
                unsigned a2 = __float_as_uint(Eb[g * 17 + 8*ks + t + 4]);
                unsigned a3 = __float_as_uint(Eb[(g + 8) * 17 + 8*ks + t + 4]);
                #pragma unroll
                for (int nt = 0; nt < 8; nt++) {
                    unsigned b0 = __float_as_uint(S1[(8*ks + t    ) * 68 + 8*nt + g]);
                    unsigned b1 = __float_as_uint(S1[(8*ks + t + 4) * 68 + 8*nt + g]);
                    mma8(c[nt], a0, a1, a2, a3, b0, b1);
                }
            }
            float* og = out + (size_t)u * 896;
            #pragma unroll
            for (int nt = 0; nt < 8; nt++) {
                int c0 = 8 * nt + 2 * t;
                *(float2*)(og + g * 64 + c0) = make_float2(c[nt][0], c[nt][1]);
                if (g < 6)
                    *(float2*)(og + (g + 8) * 64 + c0) = make_float2(c[nt][2], c[nt][3]);
            }
        }
        __syncwarp();
    }
}

// ---------------- launcher --------------------------------------------------
extern "C" void kernel_launch(void* const* d_in, const int* in_sizes, int n_in,
                              void* d_out, int out_size) {
    const float* x    = (const float*)d_in[0];
    const float* w_c  = (const float*)d_in[1];
    const float* Wq   = (const float*)d_in[2];
    const float* bq   = (const float*)d_in[3];
    const float* Wk   = (const float*)d_in[4];
    // d_in[5] = bk — provably cancelled by LayerNorm mean subtraction.
    const float* Wv   = (const float*)d_in[6];
    const float* bv   = (const float*)d_in[7];
    const float* ln_g = (const float*)d_in[8];
    const float* ln_b = (const float*)d_in[9];
    float* out = (float*)d_out;

    cudaFuncSetAttribute(attn_kernel,
                         cudaFuncAttributeMaxDynamicSharedMemorySize, SMEM_BYTES);

    precompute_kernel<<<17, 256>>>(Wq, bq, Wk, w_c);
    attn_kernel<<<NBLOCKS, 256, SMEM_BYTES>>>(x, w_c, Wv, bv, ln_g, ln_b, out);
}